// round 1
// baseline (speedup 1.0000x reference)
#include <cuda_runtime.h>
#include <cuda_bf16.h>
#include <math.h>

// ---------------- Problem constants ----------------
#define BB 8
#define TT 16
#define CC 4
#define HH 84
#define PP 14
#define GG 6          // H/P
#define NT_ 36
#define TPS_ 39
#define LL 624        // T*TPS
#define DD 512
#define NHH 8
#define DHH 64
#define NLL 6
#define DFF_ 2048
#define NRET_ 120
#define NACT_ 18
#define NREW_ 3
#define PATCH_F 784   // C*P*P
#define NPATCH 4608   // B*T*NT
#define NTOK 4992     // B*L
#define QKV3 1536

// ---------------- Scratch (static device globals; no allocation) ----------------
__device__ float g_patches[NPATCH * PATCH_F];          // 3.6M
__device__ float g_obs[NPATCH * DD];                   // 2.36M
__device__ float g_x[NTOK * DD];                       // residual stream
__device__ float g_xn[NTOK * DD];                      // layernorm out
__device__ float g_qkv[NTOK * QKV3];                   // 7.67M
__device__ float g_att[(size_t)BB * NHH * LL * LL];    // 24.92M (~100MB)
__device__ float g_o[NTOK * DD];                       // attn output
__device__ float g_h[NTOK * DFF_];                     // ffn hidden

// ---------------- im2col: frames -> patches [4608, 784] ----------------
__global__ void im2col_kernel(const float* __restrict__ frames)
{
    int idx = blockIdx.x * blockDim.x + threadIdx.x;
    const int total = NPATCH * PATCH_F;
    if (idx >= total) return;
    int f = idx % PATCH_F;
    int p = idx / PATCH_F;
    int patch = p % NT_;
    int bt = p / NT_;
    int c = f / (PP * PP);
    int rem = f % (PP * PP);
    int py = rem / PP;
    int px = rem % PP;
    int gy = patch / GG, gx = patch % GG;
    int row = gy * PP + py, col = gx * PP + px;
    g_patches[idx] = frames[(((size_t)bt * CC + c) * HH + row) * HH + col];
}

// ---------------- Generic tiled GEMM: C[M,N] = A[M,K] @ W[N,K]^T + bias (+res) (+act) ----------------
// ACT: 0 = none, 1 = exact GELU
template<int ACT, bool HAS_RES>
__global__ __launch_bounds__(256)
void gemm_bias_kernel(const float* __restrict__ A, const float* __restrict__ W,
                      const float* __restrict__ bias, const float* __restrict__ Res,
                      float* __restrict__ C, int M, int N, int K)
{
    __shared__ float As[16][64];
    __shared__ float Bs[16][64];
    const int bm = blockIdx.y * 64;
    const int bn = blockIdx.x * 64;
    const int tid = threadIdx.x;
    const int tx = tid & 15;   // col group
    const int ty = tid >> 4;   // row group
    float acc[4][4] = {};

    for (int k0 = 0; k0 < K; k0 += 16) {
        #pragma unroll
        for (int i = 0; i < 4; i++) {
            int idx = tid + i * 256;
            int m = idx >> 4, k = idx & 15;
            int gm = bm + m;
            As[k][m] = (gm < M) ? A[(size_t)gm * K + k0 + k] : 0.f;
        }
        #pragma unroll
        for (int i = 0; i < 4; i++) {
            int idx = tid + i * 256;
            int n = idx >> 4, k = idx & 15;
            int gn = bn + n;
            Bs[k][n] = (gn < N) ? W[(size_t)gn * K + k0 + k] : 0.f;
        }
        __syncthreads();
        #pragma unroll
        for (int k = 0; k < 16; k++) {
            float a[4], b[4];
            #pragma unroll
            for (int i = 0; i < 4; i++) a[i] = As[k][ty * 4 + i];
            #pragma unroll
            for (int j = 0; j < 4; j++) b[j] = Bs[k][tx * 4 + j];
            #pragma unroll
            for (int i = 0; i < 4; i++)
                #pragma unroll
                for (int j = 0; j < 4; j++)
                    acc[i][j] += a[i] * b[j];
        }
        __syncthreads();
    }

    #pragma unroll
    for (int i = 0; i < 4; i++) {
        int gm = bm + ty * 4 + i;
        if (gm >= M) continue;
        #pragma unroll
        for (int j = 0; j < 4; j++) {
            int gn = bn + tx * 4 + j;
            if (gn >= N) continue;
            float v = acc[i][j] + bias[gn];
            if (HAS_RES) v += Res[(size_t)gm * N + gn];
            if (ACT == 1) v = 0.5f * v * (1.0f + erff(v * 0.70710678118654752f));
            C[(size_t)gm * N + gn] = v;
        }
    }
}

// ---------------- Sequence assembly ----------------
__global__ void assemble_kernel(const int* __restrict__ rtg, const int* __restrict__ act,
                                const int* __restrict__ rew, const int* __restrict__ gid,
                                const float* __restrict__ re, const float* __restrict__ ae,
                                const float* __restrict__ we, const float* __restrict__ ge,
                                const float* __restrict__ pe, const float* __restrict__ te)
{
    int idx = blockIdx.x * blockDim.x + threadIdx.x;
    if (idx >= NTOK * DD) return;
    int d = idx & (DD - 1);
    int bl = idx >> 9;
    int b = bl / LL, l = bl % LL;
    int t = l / TPS_, off = l % TPS_;
    int bt = b * TT + t;
    float v;
    int type_id;
    if (off < NT_)       { v = g_obs[(size_t)(bt * NT_ + off) * DD + d]; type_id = 0; }
    else if (off == NT_) { v = re[rtg[bt] * DD + d]; type_id = 1; }
    else if (off == NT_ + 1) { v = ae[act[bt] * DD + d]; type_id = 2; }
    else                 { v = we[rew[bt] * DD + d]; type_id = 3; }
    v += pe[l * DD + d] + te[type_id * DD + d] + ge[gid[b] * DD + d];
    g_x[idx] = v;
}

// ---------------- LayerNorm (block per token, 256 threads, D=512) ----------------
__global__ __launch_bounds__(256)
void layernorm_kernel(const float* __restrict__ x, const float* __restrict__ s,
                      const float* __restrict__ bb, float* __restrict__ y)
{
    int row = blockIdx.x;
    const float* xr = x + (size_t)row * DD;
    int tid = threadIdx.x;
    float v0 = xr[tid], v1 = xr[tid + 256];
    __shared__ float red[256];
    red[tid] = v0 + v1;
    __syncthreads();
    for (int st = 128; st > 0; st >>= 1) { if (tid < st) red[tid] += red[tid + st]; __syncthreads(); }
    float mu = red[0] * (1.0f / DD);
    __syncthreads();
    float d0 = v0 - mu, d1 = v1 - mu;
    red[tid] = d0 * d0 + d1 * d1;
    __syncthreads();
    for (int st = 128; st > 0; st >>= 1) { if (tid < st) red[tid] += red[tid + st]; __syncthreads(); }
    float inv = rsqrtf(red[0] * (1.0f / DD) + 1e-5f);
    float* yr = y + (size_t)row * DD;
    yr[tid]       = d0 * inv * s[tid]       + bb[tid];
    yr[tid + 256] = d1 * inv * s[tid + 256] + bb[tid + 256];
}

// ---------------- Attention scores: att[bh, q, k] = scale * q.k + mask ----------------
__global__ __launch_bounds__(256)
void attn_scores_kernel()
{
    __shared__ float Qs[32][65];
    __shared__ float Ks[32][65];
    int bh = blockIdx.z;
    int b = bh >> 3, h = bh & 7;
    int q0 = blockIdx.y * 32, k0 = blockIdx.x * 32;
    int tid = threadIdx.x;
    for (int i = tid; i < 32 * 64; i += 256) {
        int r = i >> 6, d = i & 63;
        int qi = q0 + r;
        Qs[r][d] = (qi < LL) ? g_qkv[(size_t)(b * LL + qi) * QKV3 + h * 64 + d] : 0.f;
        int ki = k0 + r;
        Ks[r][d] = (ki < LL) ? g_qkv[(size_t)(b * LL + ki) * QKV3 + 512 + h * 64 + d] : 0.f;
    }
    __syncthreads();
    int ty = tid >> 3;     // q row 0..31
    int tx = tid & 7;      // k group (4 cols each)
    float acc[4] = {0.f, 0.f, 0.f, 0.f};
    #pragma unroll 4
    for (int d = 0; d < 64; d++) {
        float qv = Qs[ty][d];
        #pragma unroll
        for (int j = 0; j < 4; j++) acc[j] += qv * Ks[tx * 4 + j][d];
    }
    int qi = q0 + ty;
    if (qi < LL) {
        int qstep = qi / TPS_, qoff = qi - qstep * TPS_;
        #pragma unroll
        for (int j = 0; j < 4; j++) {
            int ki = k0 + tx * 4 + j;
            if (ki < LL) {
                int kstep = ki / TPS_, koff = ki - kstep * TPS_;
                bool allowed = (ki <= qi) || (qoff < NT_ && koff < NT_ && qstep == kstep);
                g_att[((size_t)bh * LL + qi) * LL + ki] = allowed ? acc[j] * 0.125f : -1e30f;
            }
        }
    }
}

// ---------------- Softmax over rows of g_att ----------------
__global__ __launch_bounds__(256)
void softmax_kernel()
{
    int row = blockIdx.x;                       // 0 .. B*NH*L-1
    float* p = g_att + (size_t)row * LL;
    int tid = threadIdx.x;
    __shared__ float red[256];
    float m = -1e30f;
    for (int i = tid; i < LL; i += 256) m = fmaxf(m, p[i]);
    red[tid] = m; __syncthreads();
    for (int st = 128; st > 0; st >>= 1) { if (tid < st) red[tid] = fmaxf(red[tid], red[tid + st]); __syncthreads(); }
    m = red[0]; __syncthreads();
    float sum = 0.f;
    for (int i = tid; i < LL; i += 256) { float e = __expf(p[i] - m); p[i] = e; sum += e; }
    red[tid] = sum; __syncthreads();
    for (int st = 128; st > 0; st >>= 1) { if (tid < st) red[tid] += red[tid + st]; __syncthreads(); }
    float inv = 1.0f / red[0];
    for (int i = tid; i < LL; i += 256) p[i] *= inv;
}

// ---------------- AV: o[b, l, h*64+d] = sum_k att * v ----------------
__global__ __launch_bounds__(256)
void attn_av_kernel()
{
    __shared__ float As[32][33];
    __shared__ float Vs[32][65];
    int bh = blockIdx.y;
    int b = bh >> 3, h = bh & 7;
    int q0 = blockIdx.x * 32;
    int tid = threadIdx.x;
    int ty = tid >> 3;      // q row
    int tx = tid & 7;       // d group (8 cols each)
    float acc[8] = {};
    for (int kc = 0; kc < LL; kc += 32) {
        for (int i = tid; i < 32 * 32; i += 256) {
            int r = i >> 5, c = i & 31;
            int qi = q0 + r, ki = kc + c;
            As[r][c] = (qi < LL && ki < LL) ? g_att[((size_t)bh * LL + qi) * LL + ki] : 0.f;
        }
        for (int i = tid; i < 32 * 64; i += 256) {
            int r = i >> 6, d = i & 63;
            int ki = kc + r;
            Vs[r][d] = (ki < LL) ? g_qkv[(size_t)(b * LL + ki) * QKV3 + 1024 + h * 64 + d] : 0.f;
        }
        __syncthreads();
        #pragma unroll
        for (int kk = 0; kk < 32; kk++) {
            float a = As[ty][kk];
            #pragma unroll
            for (int j = 0; j < 8; j++) acc[j] += a * Vs[kk][tx * 8 + j];
        }
        __syncthreads();
    }
    int qi = q0 + ty;
    if (qi < LL) {
        #pragma unroll
        for (int j = 0; j < 8; j++)
            g_o[(size_t)(b * LL + qi) * DD + h * 64 + tx * 8 + j] = acc[j];
    }
}

// ---------------- Output heads ----------------
__global__ __launch_bounds__(128)
void heads_kernel(const float* __restrict__ rw, const float* __restrict__ rb,
                  const float* __restrict__ aw, const float* __restrict__ ab,
                  const float* __restrict__ ww, const float* __restrict__ wb,
                  float* __restrict__ out)
{
    int bt = blockIdx.x;               // 0..127
    int b = bt / TT, t = bt % TT;
    __shared__ float hret[DD], hact[DD], hrew[DD];
    size_t base = (size_t)(b * LL + t * TPS_) * DD;
    for (int i = threadIdx.x; i < DD; i += 128) {
        hret[i] = g_x[base + (size_t)(NT_ - 1) * DD + i];
        hact[i] = g_x[base + (size_t)NT_ * DD + i];
        hrew[i] = g_x[base + (size_t)(NT_ + 1) * DD + i];
    }
    __syncthreads();
    const int TOT = NRET_ + NACT_ + NREW_;   // 141
    for (int o = threadIdx.x; o < TOT; o += 128) {
        if (o < NRET_) {
            float s = rb[o];
            const float* w = rw + (size_t)o * DD;
            for (int i = 0; i < DD; i++) s += hret[i] * w[i];
            out[(size_t)bt * NRET_ + o] = s;
        } else if (o < NRET_ + NACT_) {
            int n = o - NRET_;
            float s = ab[n];
            const float* w = aw + (size_t)n * DD;
            for (int i = 0; i < DD; i++) s += hact[i] * w[i];
            out[(size_t)(BB * TT * NRET_) + (size_t)bt * NACT_ + n] = s;
        } else {
            int n = o - NRET_ - NACT_;
            float s = wb[n];
            const float* w = ww + (size_t)n * DD;
            for (int i = 0; i < DD; i++) s += hrew[i] * w[i];
            out[(size_t)(BB * TT * (NRET_ + NACT_)) + (size_t)bt * NREW_ + n] = s;
        }
    }
}

// ---------------- Host launch ----------------
extern "C" void kernel_launch(void* const* d_in, const int* in_sizes, int n_in,
                              void* d_out, int out_size)
{
    const float* frames     = (const float*)d_in[0];
    const int*   rtg_bins   = (const int*)  d_in[1];
    const int*   actions    = (const int*)  d_in[2];
    const int*   reward_bins= (const int*)  d_in[3];
    const int*   game_ids   = (const int*)  d_in[4];
    const float* patch_w    = (const float*)d_in[5];
    const float* patch_b    = (const float*)d_in[6];
    const float* return_emb = (const float*)d_in[7];
    const float* action_emb = (const float*)d_in[8];
    const float* reward_emb = (const float*)d_in[9];
    const float* game_emb   = (const float*)d_in[10];
    const float* pos_emb    = (const float*)d_in[11];
    const float* type_emb   = (const float*)d_in[12];
    const float* qkv_w      = (const float*)d_in[13];
    const float* qkv_b      = (const float*)d_in[14];
    const float* out_w      = (const float*)d_in[15];
    const float* out_b      = (const float*)d_in[16];
    const float* ln1_s      = (const float*)d_in[17];
    const float* ln1_b      = (const float*)d_in[18];
    const float* ln2_s      = (const float*)d_in[19];
    const float* ln2_b      = (const float*)d_in[20];
    const float* ffn_w1     = (const float*)d_in[21];
    const float* ffn_b1     = (const float*)d_in[22];
    const float* ffn_w2     = (const float*)d_in[23];
    const float* ffn_b2     = (const float*)d_in[24];
    const float* ret_hw     = (const float*)d_in[25];
    const float* ret_hb     = (const float*)d_in[26];
    const float* act_hw     = (const float*)d_in[27];
    const float* act_hb     = (const float*)d_in[28];
    const float* rew_hw     = (const float*)d_in[29];
    const float* rew_hb     = (const float*)d_in[30];
    float* out = (float*)d_out;

    // Resolve scratch symbol addresses (no allocation, capture-safe)
    float *p_patches, *p_obs, *p_x, *p_xn, *p_qkv, *p_o, *p_h;
    cudaGetSymbolAddress((void**)&p_patches, g_patches);
    cudaGetSymbolAddress((void**)&p_obs,     g_obs);
    cudaGetSymbolAddress((void**)&p_x,       g_x);
    cudaGetSymbolAddress((void**)&p_xn,      g_xn);
    cudaGetSymbolAddress((void**)&p_qkv,     g_qkv);
    cudaGetSymbolAddress((void**)&p_o,       g_o);
    cudaGetSymbolAddress((void**)&p_h,       g_h);

    // 1. im2col
    {
        int total = NPATCH * PATCH_F;
        im2col_kernel<<<(total + 255) / 256, 256>>>(frames);
    }
    // 2. patch embed GEMM: [4608,784] x [512,784]^T -> g_obs
    {
        dim3 grid(DD / 64, NPATCH / 64);
        gemm_bias_kernel<0, false><<<grid, 256>>>(p_patches, patch_w, patch_b, nullptr,
                                                  p_obs, NPATCH, DD, PATCH_F);
    }
    // 3. assemble sequence
    {
        int total = NTOK * DD;
        assemble_kernel<<<(total + 255) / 256, 256>>>(rtg_bins, actions, reward_bins, game_ids,
                                                      return_emb, action_emb, reward_emb,
                                                      game_emb, pos_emb, type_emb);
    }
    // 4. transformer layers
    for (int i = 0; i < NLL; i++) {
        layernorm_kernel<<<NTOK, 256>>>(p_x, ln1_s + i * DD, ln1_b + i * DD, p_xn);
        {
            dim3 grid(QKV3 / 64, NTOK / 64);
            gemm_bias_kernel<0, false><<<grid, 256>>>(p_xn, qkv_w + (size_t)i * QKV3 * DD,
                                                      qkv_b + (size_t)i * QKV3, nullptr,
                                                      p_qkv, NTOK, QKV3, DD);
        }
        {
            dim3 grid((LL + 31) / 32, (LL + 31) / 32, BB * NHH);
            attn_scores_kernel<<<grid, 256>>>();
        }
        softmax_kernel<<<BB * NHH * LL, 256>>>();
        {
            dim3 grid((LL + 31) / 32, BB * NHH);
            attn_av_kernel<<<grid, 256>>>();
        }
        {
            dim3 grid(DD / 64, NTOK / 64);
            gemm_bias_kernel<0, true><<<grid, 256>>>(p_o, out_w + (size_t)i * DD * DD,
                                                     out_b + (size_t)i * DD, p_x,
                                                     p_x, NTOK, DD, DD);
        }
        layernorm_kernel<<<NTOK, 256>>>(p_x, ln2_s + i * DD, ln2_b + i * DD, p_xn);
        {
            dim3 grid(DFF_ / 64, NTOK / 64);
            gemm_bias_kernel<1, false><<<grid, 256>>>(p_xn, ffn_w1 + (size_t)i * DFF_ * DD,
                                                      ffn_b1 + (size_t)i * DFF_, nullptr,
                                                      p_h, NTOK, DFF_, DD);
        }
        {
            dim3 grid(DD / 64, NTOK / 64);
            gemm_bias_kernel<0, true><<<grid, 256>>>(p_h, ffn_w2 + (size_t)i * DD * DFF_,
                                                     ffn_b2 + (size_t)i * DD, p_x,
                                                     p_x, NTOK, DD, DFF_);
        }
    }
    // 5. heads
    heads_kernel<<<BB * TT, 128>>>(ret_hw, ret_hb, act_hw, act_hb, rew_hw, rew_hb, out);
}

// round 2
// speedup vs baseline: 1.0027x; 1.0027x over previous
#include <cuda_runtime.h>
#include <cuda_bf16.h>
#include <math.h>

// ---------------- Problem constants ----------------
#define BB 8
#define TT 16
#define CC 4
#define HH 84
#define PP 14
#define GG 6          // H/P
#define NT_ 36
#define TPS_ 39
#define LL 624        // T*TPS
#define DD 512
#define NHH 8
#define DHH 64
#define NLL 6
#define DFF_ 2048
#define NRET_ 120
#define NACT_ 18
#define NREW_ 3
#define PATCH_F 784   // C*P*P
#define NPATCH 4608   // B*T*NT
#define NTOK 4992     // B*L
#define QKV3 1536

// ---------------- Scratch (static device globals; no allocation) ----------------
__device__ float g_patches[NPATCH * PATCH_F];          // 3.6M
__device__ float g_obs[NPATCH * DD];                   // 2.36M
__device__ float g_x[NTOK * DD];                       // residual stream
__device__ float g_xn[NTOK * DD];                      // layernorm out
__device__ float g_qkv[NTOK * QKV3];                   // 7.67M
__device__ float g_att[(size_t)BB * NHH * LL * LL];    // 24.92M (~100MB)
__device__ float g_o[NTOK * DD];                       // attn output
__device__ float g_h[NTOK * DFF_];                     // ffn hidden

// ---------------- im2col: frames -> patches [4608, 784] ----------------
__global__ void im2col_kernel(const float* __restrict__ frames)
{
    int idx = blockIdx.x * blockDim.x + threadIdx.x;
    const int total = NPATCH * PATCH_F;
    if (idx >= total) return;
    int f = idx % PATCH_F;
    int p = idx / PATCH_F;
    int patch = p % NT_;
    int bt = p / NT_;
    int c = f / (PP * PP);
    int rem = f % (PP * PP);
    int py = rem / PP;
    int px = rem % PP;
    int gy = patch / GG, gx = patch % GG;
    int row = gy * PP + py, col = gx * PP + px;
    g_patches[idx] = frames[(((size_t)bt * CC + c) * HH + row) * HH + col];
}

// ---------------- Generic tiled GEMM: C[M,N] = A[M,K] @ W[N,K]^T + bias (+res) (+act) ----------------
// ACT: 0 = none, 1 = exact GELU
template<int ACT, bool HAS_RES>
__global__ __launch_bounds__(256)
void gemm_bias_kernel(const float* __restrict__ A, const float* __restrict__ W,
                      const float* __restrict__ bias, const float* __restrict__ Res,
                      float* __restrict__ C, int M, int N, int K)
{
    __shared__ float As[16][64];
    __shared__ float Bs[16][64];
    const int bm = blockIdx.y * 64;
    const int bn = blockIdx.x * 64;
    const int tid = threadIdx.x;
    const int tx = tid & 15;   // col group
    const int ty = tid >> 4;   // row group
    float acc[4][4] = {};

    for (int k0 = 0; k0 < K; k0 += 16) {
        #pragma unroll
        for (int i = 0; i < 4; i++) {
            int idx = tid + i * 256;
            int m = idx >> 4, k = idx & 15;
            int gm = bm + m;
            As[k][m] = (gm < M) ? A[(size_t)gm * K + k0 + k] : 0.f;
        }
        #pragma unroll
        for (int i = 0; i < 4; i++) {
            int idx = tid + i * 256;
            int n = idx >> 4, k = idx & 15;
            int gn = bn + n;
            Bs[k][n] = (gn < N) ? W[(size_t)gn * K + k0 + k] : 0.f;
        }
        __syncthreads();
        #pragma unroll
        for (int k = 0; k < 16; k++) {
            float a[4], b[4];
            #pragma unroll
            for (int i = 0; i < 4; i++) a[i] = As[k][ty * 4 + i];
            #pragma unroll
            for (int j = 0; j < 4; j++) b[j] = Bs[k][tx * 4 + j];
            #pragma unroll
            for (int i = 0; i < 4; i++)
                #pragma unroll
                for (int j = 0; j < 4; j++)
                    acc[i][j] += a[i] * b[j];
        }
        __syncthreads();
    }

    #pragma unroll
    for (int i = 0; i < 4; i++) {
        int gm = bm + ty * 4 + i;
        if (gm >= M) continue;
        #pragma unroll
        for (int j = 0; j < 4; j++) {
            int gn = bn + tx * 4 + j;
            if (gn >= N) continue;
            float v = acc[i][j] + bias[gn];
            if (HAS_RES) v += Res[(size_t)gm * N + gn];
            if (ACT == 1) v = 0.5f * v * (1.0f + erff(v * 0.70710678118654752f));
            C[(size_t)gm * N + gn] = v;
        }
    }
}

// ---------------- Sequence assembly ----------------
__global__ void assemble_kernel(const int* __restrict__ rtg, const int* __restrict__ act,
                                const int* __restrict__ rew, const int* __restrict__ gid,
                                const float* __restrict__ re, const float* __restrict__ ae,
                                const float* __restrict__ we, const float* __restrict__ ge,
                                const float* __restrict__ pe, const float* __restrict__ te)
{
    int idx = blockIdx.x * blockDim.x + threadIdx.x;
    if (idx >= NTOK * DD) return;
    int d = idx & (DD - 1);
    int bl = idx >> 9;
    int b = bl / LL, l = bl % LL;
    int t = l / TPS_, off = l % TPS_;
    int bt = b * TT + t;
    float v;
    int type_id;
    if (off < NT_)       { v = g_obs[(size_t)(bt * NT_ + off) * DD + d]; type_id = 0; }
    else if (off == NT_) { v = re[rtg[bt] * DD + d]; type_id = 1; }
    else if (off == NT_ + 1) { v = ae[act[bt] * DD + d]; type_id = 2; }
    else                 { v = we[rew[bt] * DD + d]; type_id = 3; }
    v += pe[l * DD + d] + te[type_id * DD + d] + ge[gid[b] * DD + d];
    g_x[idx] = v;
}

// ---------------- LayerNorm (block per token, 256 threads, D=512) ----------------
__global__ __launch_bounds__(256)
void layernorm_kernel(const float* __restrict__ x, const float* __restrict__ s,
                      const float* __restrict__ bb, float* __restrict__ y)
{
    int row = blockIdx.x;
    const float* xr = x + (size_t)row * DD;
    int tid = threadIdx.x;
    float v0 = xr[tid], v1 = xr[tid + 256];
    __shared__ float red[256];
    red[tid] = v0 + v1;
    __syncthreads();
    for (int st = 128; st > 0; st >>= 1) { if (tid < st) red[tid] += red[tid + st]; __syncthreads(); }
    float mu = red[0] * (1.0f / DD);
    __syncthreads();
    float d0 = v0 - mu, d1 = v1 - mu;
    red[tid] = d0 * d0 + d1 * d1;
    __syncthreads();
    for (int st = 128; st > 0; st >>= 1) { if (tid < st) red[tid] += red[tid + st]; __syncthreads(); }
    float inv = rsqrtf(red[0] * (1.0f / DD) + 1e-5f);
    float* yr = y + (size_t)row * DD;
    yr[tid]       = d0 * inv * s[tid]       + bb[tid];
    yr[tid + 256] = d1 * inv * s[tid + 256] + bb[tid + 256];
}

// ---------------- Attention scores: att[bh, q, k] = scale * q.k + mask ----------------
__global__ __launch_bounds__(256)
void attn_scores_kernel()
{
    __shared__ float Qs[32][65];
    __shared__ float Ks[32][65];
    int bh = blockIdx.z;
    int b = bh >> 3, h = bh & 7;
    int q0 = blockIdx.y * 32, k0 = blockIdx.x * 32;
    int tid = threadIdx.x;
    for (int i = tid; i < 32 * 64; i += 256) {
        int r = i >> 6, d = i & 63;
        int qi = q0 + r;
        Qs[r][d] = (qi < LL) ? g_qkv[(size_t)(b * LL + qi) * QKV3 + h * 64 + d] : 0.f;
        int ki = k0 + r;
        Ks[r][d] = (ki < LL) ? g_qkv[(size_t)(b * LL + ki) * QKV3 + 512 + h * 64 + d] : 0.f;
    }
    __syncthreads();
    int ty = tid >> 3;     // q row 0..31
    int tx = tid & 7;      // k group (4 cols each)
    float acc[4] = {0.f, 0.f, 0.f, 0.f};
    #pragma unroll 4
    for (int d = 0; d < 64; d++) {
        float qv = Qs[ty][d];
        #pragma unroll
        for (int j = 0; j < 4; j++) acc[j] += qv * Ks[tx * 4 + j][d];
    }
    int qi = q0 + ty;
    if (qi < LL) {
        int qstep = qi / TPS_, qoff = qi - qstep * TPS_;
        #pragma unroll
        for (int j = 0; j < 4; j++) {
            int ki = k0 + tx * 4 + j;
            if (ki < LL) {
                int kstep = ki / TPS_, koff = ki - kstep * TPS_;
                bool allowed = (ki <= qi) || (qoff < NT_ && koff < NT_ && qstep == kstep);
                g_att[((size_t)bh * LL + qi) * LL + ki] = allowed ? acc[j] * 0.125f : -1e30f;
            }
        }
    }
}

// ---------------- Softmax over rows of g_att ----------------
__global__ __launch_bounds__(256)
void softmax_kernel()
{
    int row = blockIdx.x;                       // 0 .. B*NH*L-1
    float* p = g_att + (size_t)row * LL;
    int tid = threadIdx.x;
    __shared__ float red[256];
    float m = -1e30f;
    for (int i = tid; i < LL; i += 256) m = fmaxf(m, p[i]);
    red[tid] = m; __syncthreads();
    for (int st = 128; st > 0; st >>= 1) { if (tid < st) red[tid] = fmaxf(red[tid], red[tid + st]); __syncthreads(); }
    m = red[0]; __syncthreads();
    float sum = 0.f;
    for (int i = tid; i < LL; i += 256) { float e = __expf(p[i] - m); p[i] = e; sum += e; }
    red[tid] = sum; __syncthreads();
    for (int st = 128; st > 0; st >>= 1) { if (tid < st) red[tid] += red[tid + st]; __syncthreads(); }
    float inv = 1.0f / red[0];
    for (int i = tid; i < LL; i += 256) p[i] *= inv;
}

// ---------------- AV: o[b, l, h*64+d] = sum_k att * v ----------------
__global__ __launch_bounds__(256)
void attn_av_kernel()
{
    __shared__ float As[32][33];
    __shared__ float Vs[32][65];
    int bh = blockIdx.y;
    int b = bh >> 3, h = bh & 7;
    int q0 = blockIdx.x * 32;
    int tid = threadIdx.x;
    int ty = tid >> 3;      // q row
    int tx = tid & 7;       // d group (8 cols each)
    float acc[8] = {};
    for (int kc = 0; kc < LL; kc += 32) {
        for (int i = tid; i < 32 * 32; i += 256) {
            int r = i >> 5, c = i & 31;
            int qi = q0 + r, ki = kc + c;
            As[r][c] = (qi < LL && ki < LL) ? g_att[((size_t)bh * LL + qi) * LL + ki] : 0.f;
        }
        for (int i = tid; i < 32 * 64; i += 256) {
            int r = i >> 6, d = i & 63;
            int ki = kc + r;
            Vs[r][d] = (ki < LL) ? g_qkv[(size_t)(b * LL + ki) * QKV3 + 1024 + h * 64 + d] : 0.f;
        }
        __syncthreads();
        #pragma unroll
        for (int kk = 0; kk < 32; kk++) {
            float a = As[ty][kk];
            #pragma unroll
            for (int j = 0; j < 8; j++) acc[j] += a * Vs[kk][tx * 8 + j];
        }
        __syncthreads();
    }
    int qi = q0 + ty;
    if (qi < LL) {
        #pragma unroll
        for (int j = 0; j < 8; j++)
            g_o[(size_t)(b * LL + qi) * DD + h * 64 + tx * 8 + j] = acc[j];
    }
}

// ---------------- Output heads ----------------
__global__ __launch_bounds__(128)
void heads_kernel(const float* __restrict__ rw, const float* __restrict__ rb,
                  const float* __restrict__ aw, const float* __restrict__ ab,
                  const float* __restrict__ ww, const float* __restrict__ wb,
                  float* __restrict__ out)
{
    int bt = blockIdx.x;               // 0..127
    int b = bt / TT, t = bt % TT;
    __shared__ float hret[DD], hact[DD], hrew[DD];
    size_t base = (size_t)(b * LL + t * TPS_) * DD;
    for (int i = threadIdx.x; i < DD; i += 128) {
        hret[i] = g_x[base + (size_t)(NT_ - 1) * DD + i];
        hact[i] = g_x[base + (size_t)NT_ * DD + i];
        hrew[i] = g_x[base + (size_t)(NT_ + 1) * DD + i];
    }
    __syncthreads();
    const int TOT = NRET_ + NACT_ + NREW_;   // 141
    for (int o = threadIdx.x; o < TOT; o += 128) {
        if (o < NRET_) {
            float s = rb[o];
            const float* w = rw + (size_t)o * DD;
            for (int i = 0; i < DD; i++) s += hret[i] * w[i];
            out[(size_t)bt * NRET_ + o] = s;
        } else if (o < NRET_ + NACT_) {
            int n = o - NRET_;
            float s = ab[n];
            const float* w = aw + (size_t)n * DD;
            for (int i = 0; i < DD; i++) s += hact[i] * w[i];
            out[(size_t)(BB * TT * NRET_) + (size_t)bt * NACT_ + n] = s;
        } else {
            int n = o - NRET_ - NACT_;
            float s = wb[n];
            const float* w = ww + (size_t)n * DD;
            for (int i = 0; i < DD; i++) s += hrew[i] * w[i];
            out[(size_t)(BB * TT * (NRET_ + NACT_)) + (size_t)bt * NREW_ + n] = s;
        }
    }
}

// ---------------- Host launch ----------------
extern "C" void kernel_launch(void* const* d_in, const int* in_sizes, int n_in,
                              void* d_out, int out_size)
{
    const float* frames     = (const float*)d_in[0];
    const int*   rtg_bins   = (const int*)  d_in[1];
    const int*   actions    = (const int*)  d_in[2];
    const int*   reward_bins= (const int*)  d_in[3];
    const int*   game_ids   = (const int*)  d_in[4];
    const float* patch_w    = (const float*)d_in[5];
    const float* patch_b    = (const float*)d_in[6];
    const float* return_emb = (const float*)d_in[7];
    const float* action_emb = (const float*)d_in[8];
    const float* reward_emb = (const float*)d_in[9];
    const float* game_emb   = (const float*)d_in[10];
    const float* pos_emb    = (const float*)d_in[11];
    const float* type_emb   = (const float*)d_in[12];
    const float* qkv_w      = (const float*)d_in[13];
    const float* qkv_b      = (const float*)d_in[14];
    const float* out_w      = (const float*)d_in[15];
    const float* out_b      = (const float*)d_in[16];
    const float* ln1_s      = (const float*)d_in[17];
    const float* ln1_b      = (const float*)d_in[18];
    const float* ln2_s      = (const float*)d_in[19];
    const float* ln2_b      = (const float*)d_in[20];
    const float* ffn_w1     = (const float*)d_in[21];
    const float* ffn_b1     = (const float*)d_in[22];
    const float* ffn_w2     = (const float*)d_in[23];
    const float* ffn_b2     = (const float*)d_in[24];
    const float* ret_hw     = (const float*)d_in[25];
    const float* ret_hb     = (const float*)d_in[26];
    const float* act_hw     = (const float*)d_in[27];
    const float* act_hb     = (const float*)d_in[28];
    const float* rew_hw     = (const float*)d_in[29];
    const float* rew_hb     = (const float*)d_in[30];
    float* out = (float*)d_out;

    // Resolve scratch symbol addresses (no allocation, capture-safe)
    float *p_patches, *p_obs, *p_x, *p_xn, *p_qkv, *p_o, *p_h;
    cudaGetSymbolAddress((void**)&p_patches, g_patches);
    cudaGetSymbolAddress((void**)&p_obs,     g_obs);
    cudaGetSymbolAddress((void**)&p_x,       g_x);
    cudaGetSymbolAddress((void**)&p_xn,      g_xn);
    cudaGetSymbolAddress((void**)&p_qkv,     g_qkv);
    cudaGetSymbolAddress((void**)&p_o,       g_o);
    cudaGetSymbolAddress((void**)&p_h,       g_h);

    // 1. im2col
    {
        int total = NPATCH * PATCH_F;
        im2col_kernel<<<(total + 255) / 256, 256>>>(frames);
    }
    // 2. patch embed GEMM: [4608,784] x [512,784]^T -> g_obs
    {
        dim3 grid(DD / 64, NPATCH / 64);
        gemm_bias_kernel<0, false><<<grid, 256>>>(p_patches, patch_w, patch_b, nullptr,
                                                  p_obs, NPATCH, DD, PATCH_F);
    }
    // 3. assemble sequence
    {
        int total = NTOK * DD;
        assemble_kernel<<<(total + 255) / 256, 256>>>(rtg_bins, actions, reward_bins, game_ids,
                                                      return_emb, action_emb, reward_emb,
                                                      game_emb, pos_emb, type_emb);
    }
    // 4. transformer layers
    for (int i = 0; i < NLL; i++) {
        layernorm_kernel<<<NTOK, 256>>>(p_x, ln1_s + i * DD, ln1_b + i * DD, p_xn);
        {
            dim3 grid(QKV3 / 64, NTOK / 64);
            gemm_bias_kernel<0, false><<<grid, 256>>>(p_xn, qkv_w + (size_t)i * QKV3 * DD,
                                                      qkv_b + (size_t)i * QKV3, nullptr,
                                                      p_qkv, NTOK, QKV3, DD);
        }
        {
            dim3 grid((LL + 31) / 32, (LL + 31) / 32, BB * NHH);
            attn_scores_kernel<<<grid, 256>>>();
        }
        softmax_kernel<<<BB * NHH * LL, 256>>>();
        {
            dim3 grid((LL + 31) / 32, BB * NHH);
            attn_av_kernel<<<grid, 256>>>();
        }
        {
            dim3 grid(DD / 64, NTOK / 64);
            gemm_bias_kernel<0, true><<<grid, 256>>>(p_o, out_w + (size_t)i * DD * DD,
                                                     out_b + (size_t)i * DD, p_x,
                                                     p_x, NTOK, DD, DD);
        }
        layernorm_kernel<<<NTOK, 256>>>(p_x, ln2_s + i * DD, ln2_b + i * DD, p_xn);
        {
            dim3 grid(DFF_ / 64, NTOK / 64);
            gemm_bias_kernel<1, false><<<grid, 256>>>(p_xn, ffn_w1 + (size_t)i * DFF_ * DD,
                                                      ffn_b1 + (size_t)i * DFF_, nullptr,
                                                      p_h, NTOK, DFF_, DD);
        }
        {
            dim3 grid(DD / 64, NTOK / 64);
            gemm_bias_kernel<0, true><<<grid, 256>>>(p_h, ffn_w2 + (size_t)i * DD * DFF_,
                                                     ffn_b2 + (size_t)i * DD, p_x,
                                                     p_x, NTOK, DD, DFF_);
        }
    }
    // 5. heads
    heads_kernel<<<BB * TT, 128>>>(ret_hw, ret_hb, act_hw, act_hb, rew_hw, rew_hb, out);
}

// round 3
// speedup vs baseline: 2.1584x; 2.1526x over previous
#include <cuda_runtime.h>
#include <cuda_bf16.h>
#include <math.h>

// ---------------- Problem constants ----------------
#define BB 8
#define TT 16
#define CC 4
#define HH 84
#define PP 14
#define GG 6          // H/P
#define NT_ 36
#define TPS_ 39
#define LL 624        // T*TPS
#define DD 512
#define NHH 8
#define DHH 64
#define NLL 6
#define DFF_ 2048
#define NRET_ 120
#define NACT_ 18
#define NREW_ 3
#define PATCH_F 784   // C*P*P
#define NPATCH 4608   // B*T*NT
#define NTOK 4992     // B*L
#define QKV3 1536

// ---------------- Scratch (static device globals; no allocation) ----------------
__device__ float g_patches[NPATCH * PATCH_F];
__device__ float g_obs[NPATCH * DD];
__device__ float g_x[NTOK * DD];
__device__ float g_xn[NTOK * DD];
__device__ float g_qkv[NTOK * QKV3];
__device__ float g_att[(size_t)BB * NHH * LL * LL];
__device__ float g_o[NTOK * DD];
__device__ float g_h[NTOK * DFF_];

// ---------------- helpers ----------------
__device__ __forceinline__ unsigned f2tf32(float x) {
    unsigned r;
    asm("cvt.rna.tf32.f32 %0, %1;" : "=r"(r) : "f"(x));
    return r;
}

__device__ __forceinline__ void mma_tf32(float* c, const unsigned* a, const unsigned* b) {
    asm volatile(
        "mma.sync.aligned.m16n8k8.row.col.f32.tf32.tf32.f32 "
        "{%0,%1,%2,%3}, {%4,%5,%6,%7}, {%8,%9}, {%0,%1,%2,%3};"
        : "+f"(c[0]), "+f"(c[1]), "+f"(c[2]), "+f"(c[3])
        : "r"(a[0]), "r"(a[1]), "r"(a[2]), "r"(a[3]), "r"(b[0]), "r"(b[1]));
}

// ---------------- im2col ----------------
__global__ void im2col_kernel(const float* __restrict__ frames)
{
    int idx = blockIdx.x * blockDim.x + threadIdx.x;
    const int total = NPATCH * PATCH_F;
    if (idx >= total) return;
    int f = idx % PATCH_F;
    int p = idx / PATCH_F;
    int patch = p % NT_;
    int bt = p / NT_;
    int c = f / (PP * PP);
    int rem = f % (PP * PP);
    int py = rem / PP;
    int px = rem % PP;
    int gy = patch / GG, gx = patch % GG;
    int row = gy * PP + py, col = gx * PP + px;
    g_patches[idx] = frames[(((size_t)bt * CC + c) * HH + row) * HH + col];
}

// ---------------- tf32 tensor-core GEMM ----------------
// C[M,N] = A[M,K] @ B[N,K]^T (+bias)(+res)(+act / mask)
// A row-major (lda), B row-major over [N,K] (ldb), C row-major (ldc).
// EPI: 0 = +bias
//      1 = +bias, GELU
//      2 = +bias, +Res (Res uses ldc layout)
//      3 = attention scores: *0.125, causal/obs mask (row=q, col=k)
//      4 = plain (AV)
// NTILES: n-tiles of 8 per warp; BN = 16*NTILES (8 warps as 4m x 2n, warp tile 32 x 8*NTILES)
template<int EPI, int NTILES>
__global__ __launch_bounds__(256)
void gemm_tf32_kernel(const float* __restrict__ A, long lda, long batchA,
                      const float* __restrict__ Bm, long ldb, long batchB,
                      float* __restrict__ C, long ldc, long batchC,
                      int M, int N, int K,
                      const float* __restrict__ bias,
                      const float* __restrict__ Res)
{
    constexpr int BM = 128, BK = 16;
    constexpr int WN = NTILES * 8;
    constexpr int BN = 2 * WN;
    __shared__ float As[BM][BK + 4];        // [m][k], stride 20
    __shared__ float Bs[BK][BN + 8];        // [k][n], stride BN+8

    const int bz = blockIdx.z;
    A  += (size_t)bz * batchA;
    Bm += (size_t)bz * batchB;
    C  += (size_t)bz * batchC;

    const int bm = blockIdx.y * BM;
    const int bn = blockIdx.x * BN;
    const int tid = threadIdx.x;
    const int lane = tid & 31;
    const int wid = tid >> 5;
    const int wm = (wid & 3) * 32;
    const int wn = (wid >> 2) * WN;
    const int g = lane >> 2;
    const int tig = lane & 3;

    float acc[2][NTILES][4] = {};

    for (int k0 = 0; k0 < K; k0 += BK) {
        // load A tile: 128x16 = 512 float4, 2 per thread
        #pragma unroll
        for (int i = 0; i < 2; i++) {
            int idx = tid + i * 256;
            int m = idx >> 2, kv = idx & 3;
            int gm = bm + m;
            float4 v = make_float4(0.f, 0.f, 0.f, 0.f);
            if (gm < M) v = *(const float4*)(A + (size_t)gm * lda + k0 + kv * 4);
            As[m][kv * 4 + 0] = __uint_as_float(f2tf32(v.x));
            As[m][kv * 4 + 1] = __uint_as_float(f2tf32(v.y));
            As[m][kv * 4 + 2] = __uint_as_float(f2tf32(v.z));
            As[m][kv * 4 + 3] = __uint_as_float(f2tf32(v.w));
        }
        // load B tile: BN x 16 -> transpose into Bs[k][n]
        #pragma unroll
        for (int i = 0; i < (BN * 4 + 255) / 256; i++) {
            int idx = tid + i * 256;
            if (idx < BN * 4) {
                int n = idx >> 2, kv = idx & 3;
                int gn = bn + n;
                float4 v = make_float4(0.f, 0.f, 0.f, 0.f);
                if (gn < N) v = *(const float4*)(Bm + (size_t)gn * ldb + k0 + kv * 4);
                Bs[kv * 4 + 0][n] = __uint_as_float(f2tf32(v.x));
                Bs[kv * 4 + 1][n] = __uint_as_float(f2tf32(v.y));
                Bs[kv * 4 + 2][n] = __uint_as_float(f2tf32(v.z));
                Bs[kv * 4 + 3][n] = __uint_as_float(f2tf32(v.w));
            }
        }
        __syncthreads();

        #pragma unroll
        for (int k8 = 0; k8 < BK; k8 += 8) {
            unsigned af[2][4];
            #pragma unroll
            for (int mt = 0; mt < 2; mt++) {
                int r0 = wm + mt * 16 + g;
                af[mt][0] = __float_as_uint(As[r0][k8 + tig]);
                af[mt][1] = __float_as_uint(As[r0 + 8][k8 + tig]);
                af[mt][2] = __float_as_uint(As[r0][k8 + tig + 4]);
                af[mt][3] = __float_as_uint(As[r0 + 8][k8 + tig + 4]);
            }
            #pragma unroll
            for (int nt = 0; nt < NTILES; nt++) {
                unsigned bf[2];
                bf[0] = __float_as_uint(Bs[k8 + tig][wn + nt * 8 + g]);
                bf[1] = __float_as_uint(Bs[k8 + tig + 4][wn + nt * 8 + g]);
                mma_tf32(acc[0][nt], af[0], bf);
                mma_tf32(acc[1][nt], af[1], bf);
            }
        }
        __syncthreads();
    }

    // epilogue
    #pragma unroll
    for (int mt = 0; mt < 2; mt++) {
        #pragma unroll
        for (int nt = 0; nt < NTILES; nt++) {
            #pragma unroll
            for (int ci = 0; ci < 4; ci++) {
                int row = bm + wm + mt * 16 + g + ((ci >> 1) ? 8 : 0);
                int col = bn + wn + nt * 8 + tig * 2 + (ci & 1);
                if (row < M && col < N) {
                    float v = acc[mt][nt][ci];
                    if (EPI == 0 || EPI == 1 || EPI == 2) v += bias[col];
                    if (EPI == 2) v += Res[(size_t)row * ldc + col];
                    if (EPI == 1) v = 0.5f * v * (1.0f + erff(v * 0.70710678118654752f));
                    if (EPI == 3) {
                        v *= 0.125f;
                        int qi = row, ki = col;
                        int qstep = qi / TPS_, qoff = qi - qstep * TPS_;
                        int kstep = ki / TPS_, koff = ki - kstep * TPS_;
                        bool allowed = (ki <= qi) ||
                                       (qoff < NT_ && koff < NT_ && qstep == kstep);
                        if (!allowed) v = -1e30f;
                    }
                    C[(size_t)row * ldc + col] = v;
                }
            }
        }
    }
}

// ---------------- Sequence assembly ----------------
__global__ void assemble_kernel(const int* __restrict__ rtg, const int* __restrict__ act,
                                const int* __restrict__ rew, const int* __restrict__ gid,
                                const float* __restrict__ re, const float* __restrict__ ae,
                                const float* __restrict__ we, const float* __restrict__ ge,
                                const float* __restrict__ pe, const float* __restrict__ te)
{
    int idx = blockIdx.x * blockDim.x + threadIdx.x;
    if (idx >= NTOK * DD) return;
    int d = idx & (DD - 1);
    int bl = idx >> 9;
    int b = bl / LL, l = bl % LL;
    int t = l / TPS_, off = l % TPS_;
    int bt = b * TT + t;
    float v;
    int type_id;
    if (off < NT_)       { v = g_obs[(size_t)(bt * NT_ + off) * DD + d]; type_id = 0; }
    else if (off == NT_) { v = re[rtg[bt] * DD + d]; type_id = 1; }
    else if (off == NT_ + 1) { v = ae[act[bt] * DD + d]; type_id = 2; }
    else                 { v = we[rew[bt] * DD + d]; type_id = 3; }
    v += pe[l * DD + d] + te[type_id * DD + d] + ge[gid[b] * DD + d];
    g_x[idx] = v;
}

// ---------------- LayerNorm ----------------
__global__ __launch_bounds__(256)
void layernorm_kernel(const float* __restrict__ x, const float* __restrict__ s,
                      const float* __restrict__ bb, float* __restrict__ y)
{
    int row = blockIdx.x;
    const float* xr = x + (size_t)row * DD;
    int tid = threadIdx.x;
    float v0 = xr[tid], v1 = xr[tid + 256];
    __shared__ float red[256];
    red[tid] = v0 + v1;
    __syncthreads();
    for (int st = 128; st > 0; st >>= 1) { if (tid < st) red[tid] += red[tid + st]; __syncthreads(); }
    float mu = red[0] * (1.0f / DD);
    __syncthreads();
    float d0 = v0 - mu, d1 = v1 - mu;
    red[tid] = d0 * d0 + d1 * d1;
    __syncthreads();
    for (int st = 128; st > 0; st >>= 1) { if (tid < st) red[tid] += red[tid + st]; __syncthreads(); }
    float inv = rsqrtf(red[0] * (1.0f / DD) + 1e-5f);
    float* yr = y + (size_t)row * DD;
    yr[tid]       = d0 * inv * s[tid]       + bb[tid];
    yr[tid + 256] = d1 * inv * s[tid + 256] + bb[tid + 256];
}

// ---------------- Softmax ----------------
__global__ __launch_bounds__(256)
void softmax_kernel()
{
    int row = blockIdx.x;
    float* p = g_att + (size_t)row * LL;
    int tid = threadIdx.x;
    __shared__ float red[256];
    float m = -1e30f;
    for (int i = tid; i < LL; i += 256) m = fmaxf(m, p[i]);
    red[tid] = m; __syncthreads();
    for (int st = 128; st > 0; st >>= 1) { if (tid < st) red[tid] = fmaxf(red[tid], red[tid + st]); __syncthreads(); }
    m = red[0]; __syncthreads();
    float sum = 0.f;
    for (int i = tid; i < LL; i += 256) { float e = __expf(p[i] - m); p[i] = e; sum += e; }
    red[tid] = sum; __syncthreads();
    for (int st = 128; st > 0; st >>= 1) { if (tid < st) red[tid] += red[tid + st]; __syncthreads(); }
    float inv = 1.0f / red[0];
    for (int i = tid; i < LL; i += 256) p[i] *= inv;
}

// ---------------- Output heads ----------------
__global__ __launch_bounds__(128)
void heads_kernel(const float* __restrict__ rw, const float* __restrict__ rb,
                  const float* __restrict__ aw, const float* __restrict__ ab,
                  const float* __restrict__ ww, const float* __restrict__ wb,
                  float* __restrict__ out)
{
    int bt = blockIdx.x;
    int b = bt / TT, t = bt % TT;
    __shared__ float hret[DD], hact[DD], hrew[DD];
    size_t base = (size_t)(b * LL + t * TPS_) * DD;
    for (int i = threadIdx.x; i < DD; i += 128) {
        hret[i] = g_x[base + (size_t)(NT_ - 1) * DD + i];
        hact[i] = g_x[base + (size_t)NT_ * DD + i];
        hrew[i] = g_x[base + (size_t)(NT_ + 1) * DD + i];
    }
    __syncthreads();
    const int TOT = NRET_ + NACT_ + NREW_;
    for (int o = threadIdx.x; o < TOT; o += 128) {
        if (o < NRET_) {
            float s = rb[o];
            const float* w = rw + (size_t)o * DD;
            for (int i = 0; i < DD; i++) s += hret[i] * w[i];
            out[(size_t)bt * NRET_ + o] = s;
        } else if (o < NRET_ + NACT_) {
            int n = o - NRET_;
            float s = ab[n];
            const float* w = aw + (size_t)n * DD;
            for (int i = 0; i < DD; i++) s += hact[i] * w[i];
            out[(size_t)(BB * TT * NRET_) + (size_t)bt * NACT_ + n] = s;
        } else {
            int n = o - NRET_ - NACT_;
            float s = wb[n];
            const float* w = ww + (size_t)n * DD;
            for (int i = 0; i < DD; i++) s += hrew[i] * w[i];
            out[(size_t)(BB * TT * (NRET_ + NACT_)) + (size_t)bt * NREW_ + n] = s;
        }
    }
}

// ---------------- Host launch ----------------
extern "C" void kernel_launch(void* const* d_in, const int* in_sizes, int n_in,
                              void* d_out, int out_size)
{
    const float* frames     = (const float*)d_in[0];
    const int*   rtg_bins   = (const int*)  d_in[1];
    const int*   actions    = (const int*)  d_in[2];
    const int*   reward_bins= (const int*)  d_in[3];
    const int*   game_ids   = (const int*)  d_in[4];
    const float* patch_w    = (const float*)d_in[5];
    const float* patch_b    = (const float*)d_in[6];
    const float* return_emb = (const float*)d_in[7];
    const float* action_emb = (const float*)d_in[8];
    const float* reward_emb = (const float*)d_in[9];
    const float* game_emb   = (const float*)d_in[10];
    const float* pos_emb    = (const float*)d_in[11];
    const float* type_emb   = (const float*)d_in[12];
    const float* qkv_w      = (const float*)d_in[13];
    const float* qkv_b      = (const float*)d_in[14];
    const float* out_w      = (const float*)d_in[15];
    const float* out_b      = (const float*)d_in[16];
    const float* ln1_s      = (const float*)d_in[17];
    const float* ln1_b      = (const float*)d_in[18];
    const float* ln2_s      = (const float*)d_in[19];
    const float* ln2_b      = (const float*)d_in[20];
    const float* ffn_w1     = (const float*)d_in[21];
    const float* ffn_b1     = (const float*)d_in[22];
    const float* ffn_w2     = (const float*)d_in[23];
    const float* ffn_b2     = (const float*)d_in[24];
    const float* ret_hw     = (const float*)d_in[25];
    const float* ret_hb     = (const float*)d_in[26];
    const float* act_hw     = (const float*)d_in[27];
    const float* act_hb     = (const float*)d_in[28];
    const float* rew_hw     = (const float*)d_in[29];
    const float* rew_hb     = (const float*)d_in[30];
    float* out = (float*)d_out;

    float *p_patches, *p_obs, *p_x, *p_xn, *p_qkv, *p_att, *p_o, *p_h;
    cudaGetSymbolAddress((void**)&p_patches, g_patches);
    cudaGetSymbolAddress((void**)&p_obs,     g_obs);
    cudaGetSymbolAddress((void**)&p_x,       g_x);
    cudaGetSymbolAddress((void**)&p_xn,      g_xn);
    cudaGetSymbolAddress((void**)&p_qkv,     g_qkv);
    cudaGetSymbolAddress((void**)&p_att,     g_att);
    cudaGetSymbolAddress((void**)&p_o,       g_o);
    cudaGetSymbolAddress((void**)&p_h,       g_h);

    // 1. im2col
    {
        int total = NPATCH * PATCH_F;
        im2col_kernel<<<(total + 255) / 256, 256>>>(frames);
    }
    // 2. patch embed: [4608,784] x [512,784]^T
    {
        dim3 grid(DD / 128, NPATCH / 128, 1);
        gemm_tf32_kernel<0, 8><<<grid, 256>>>(p_patches, PATCH_F, 0,
                                              patch_w, PATCH_F, 0,
                                              p_obs, DD, 0,
                                              NPATCH, DD, PATCH_F,
                                              patch_b, nullptr);
    }
    // 3. assemble
    {
        int total = NTOK * DD;
        assemble_kernel<<<(total + 255) / 256, 256>>>(rtg_bins, actions, reward_bins, game_ids,
                                                      return_emb, action_emb, reward_emb,
                                                      game_emb, pos_emb, type_emb);
    }
    // 4. layers
    for (int i = 0; i < NLL; i++) {
        layernorm_kernel<<<NTOK, 256>>>(p_x, ln1_s + i * DD, ln1_b + i * DD, p_xn);
        // QKV: [4992,512] x [1536,512]^T
        {
            dim3 grid(QKV3 / 128, NTOK / 128, 1);
            gemm_tf32_kernel<0, 8><<<grid, 256>>>(p_xn, DD, 0,
                                                  qkv_w + (size_t)i * QKV3 * DD, DD, 0,
                                                  p_qkv, QKV3, 0,
                                                  NTOK, QKV3, DD,
                                                  qkv_b + (size_t)i * QKV3, nullptr);
        }
        // scores: per (b,h): Q[624,64] x K[624,64]^T -> att
        {
            dim3 grid((LL + 127) / 128, (LL + 127) / 128, BB * NHH);
            // batch z = b*8+h: A offset = b*LL*QKV3 + h*64 ... strides differ for b vs h,
            // so launch per-b with z = h? Instead use combined: batchA over h works only if
            // b folded. Launch 8 z-batches per b is messy; use one launch with z=64 and
            // per-z pointer math done via batch strides: stride over h = 64, over b = LL*QKV3.
            // 64 = 8*8: z = b*8 + h -> offset = b*(LL*QKV3) + h*64. Not a single stride.
            // Handle by launching per-b (8 small launches).
        }
        for (int b = 0; b < BB; b++) {
            dim3 grid((LL + 127) / 128, (LL + 127) / 128, NHH);
            gemm_tf32_kernel<3, 8><<<grid, 256>>>(
                p_qkv + (size_t)b * LL * QKV3, QKV3, 64,
                p_qkv + (size_t)b * LL * QKV3 + 512, QKV3, 64,
                p_att + (size_t)b * NHH * LL * LL, LL, (long)LL * LL,
                LL, LL, DHH,
                nullptr, nullptr);
        }
        softmax_kernel<<<BB * NHH * LL, 256>>>();
        // AV: per (b,h): att[624,624] x V^T ... C = att @ V, V as B[N=64,K=624]? We need
        // o[q][d] = sum_k att[q][k] V[k][d]; B[n][k] = V[k][n] is a transpose — but our
        // kernel reads B[n][k] row-major. Instead feed B = V with ldb trick is invalid.
        // Solution: the kernel computes A @ B^T where B is [N,K] row-major. We need
        // B^T[k][n] = V[k][n], i.e. B[n][k] = V[k][n]: element at Bm + n*ldb + k must be
        // V[k][n] = g_qkv[...+ k*QKV3 + 1024 + h*64 + n]  -> ldb = 1 and k-stride QKV3.
        // Not expressible. So transpose via scores-style: o^T? Use separate AV below.
        for (int b = 0; b < BB; b++) {
            // AV via gemm with A=att (row q, k) and B=V^T: we pass V with "n-major" by
            // swapping roles: compute o^T[d][q]? Keep simple: dedicated kernel call with
            // NT-swap — we instead use the kernel on (A=att, B=Vt) where Vt rows are d.
            // Vt[d][k] = V[k][d]: stride over d is 1, over k is QKV3 -> again not row-major.
            // => use EPI=4 with ldb = QKV3 and treat B row index as k? That computes
            // C[m][n] = sum_k A[m][k]*B[n][k]; we want sum_k A[m][k]*V[k][n].
            // Choose B[n][k] := row n at (1024 + h*64 + n) + k*QKV3 — a column. ldb=1 fails.
            (void)0;
        }
        // AV fallback: SIMT kernel below (separate), launched here.
        {
            extern void launch_av(float*, float*, float*); // forward decl dummy (unused)
        }
        // actual AV launch happens via attn_av_kernel declared after (see below)
        {
            void attn_av_launch(); // placeholder
        }
        // (real launch)
        {
            dim3 grid((LL + 31) / 32, BB * NHH);
            extern __global__ void attn_av_kernel();
            attn_av_kernel<<<grid, 256>>>();
        }
        // out proj: [4992,512] x [512,512]^T + residual
        {
            dim3 grid(DD / 128, NTOK / 128, 1);
            gemm_tf32_kernel<2, 8><<<grid, 256>>>(p_o, DD, 0,
                                                  out_w + (size_t)i * DD * DD, DD, 0,
                                                  p_x, DD, 0,
                                                  NTOK, DD, DD,
                                                  out_b + (size_t)i * DD, p_x);
        }
        layernorm_kernel<<<NTOK, 256>>>(p_x, ln2_s + i * DD, ln2_b + i * DD, p_xn);
        // ffn1: [4992,512] x [2048,512]^T, GELU
        {
            dim3 grid(DFF_ / 128, NTOK / 128, 1);
            gemm_tf32_kernel<1, 8><<<grid, 256>>>(p_xn, DD, 0,
                                                  ffn_w1 + (size_t)i * DFF_ * DD, DD, 0,
                                                  p_h, DFF_, 0,
                                                  NTOK, DFF_, DD,
                                                  ffn_b1 + (size_t)i * DFF_, nullptr);
        }
        // ffn2: [4992,2048] x [512,2048]^T + residual
        {
            dim3 grid(DD / 128, NTOK / 128, 1);
            gemm_tf32_kernel<2, 8><<<grid, 256>>>(p_h, DFF_, 0,
                                                  ffn_w2 + (size_t)i * DD * DFF_, DFF_, 0,
                                                  p_x, DD, 0,
                                                  NTOK, DD, DFF_,
                                                  ffn_b2 + (size_t)i * DD, p_x);
        }
    }
    // 5. heads
    heads_kernel<<<BB * TT, 128>>>(ret_hw, ret_hb, act_hw, act_hb, rew_hw, rew_hb, out);
}

// ---------------- AV (SIMT; V^T layout not expressible in the tf32 GEMM's B format) ----
__global__ __launch_bounds__(256)
void attn_av_kernel()
{
    __shared__ float As[32][33];
    __shared__ float Vs[32][65];
    int bh = blockIdx.y;
    int b = bh >> 3, h = bh & 7;
    int q0 = blockIdx.x * 32;
    int tid = threadIdx.x;
    int ty = tid >> 3;
    int tx = tid & 7;
    float acc[8] = {};
    for (int kc = 0; kc < LL; kc += 32) {
        for (int i = tid; i < 32 * 32; i += 256) {
            int r = i >> 5, c = i & 31;
            int qi = q0 + r, ki = kc + c;
            As[r][c] = (qi < LL && ki < LL) ? g_att[((size_t)bh * LL + qi) * LL + ki] : 0.f;
        }
        for (int i = tid; i < 32 * 64; i += 256) {
            int r = i >> 6, d = i & 63;
            int ki = kc + r;
            Vs[r][d] = (ki < LL) ? g_qkv[(size_t)(b * LL + ki) * QKV3 + 1024 + h * 64 + d] : 0.f;
        }
        __syncthreads();
        #pragma unroll
        for (int kk = 0; kk < 32; kk++) {
            float a = As[ty][kk];
            #pragma unroll
            for (int j = 0; j < 8; j++) acc[j] += a * Vs[kk][tx * 8 + j];
        }
        __syncthreads();
    }
    int qi = q0 + ty;
    if (qi < LL) {
        #pragma unroll
        for (int j = 0; j < 8; j++)
            g_o[(size_t)(b * LL + qi) * DD + h * 64 + tx * 8 + j] = acc[j];
    }
}